// round 4
// baseline (speedup 1.0000x reference)
#include <cuda_runtime.h>

// VSampling: voxel-grid mean pooling.
//   inputs : coord [N,3] float32, offset [B] int32 (cumulative batch offsets)
//   outputs: n_p [N,3] f32 (voxel means in sorted-key order, zero padded),
//            n_o [B] (cumulative voxels per batch), counts [N] (pts per voxel)
//   packed into d_out as float32: [n_p | n_o | counts]  (fallback: n_p only)
//
// KEY ARITHMETIC NOTE: XLA rewrites x/0.05f -> x * (1/0.05f), and
// f32(1/f32(0.05)) == 20.0f exactly. We must use multiply-by-20.0f to match
// the reference's voxel assignment bit-for-bit.

#define RINV 20.0f      // f32 reciprocal of f32(0.05), exactly representable
#define MAXB 32
#define CHUNK 8192
#define NSCAN 3072
#define MAX_KEYS (NSCAN * CHUNK)   // 25,165,824 cells capacity (G up to ~116)

// Dense voxel accumulator: {sum_x, sum_y, sum_z, count}
__device__ float4  g_cell[MAX_KEYS];
__device__ unsigned g_minbits[MAXB * 3];
__device__ unsigned g_maxbits[MAXB * 3];
__device__ int g_G, g_G3, g_NKEY;
__device__ int g_bcnt[NSCAN];
__device__ int g_boff[NSCAN + 1];

// ---------------------------------------------------------------- init
__global__ void k_init() {
    int t = threadIdx.x;
    if (t < MAXB * 3) { g_minbits[t] = 0x7f800000u; g_maxbits[t] = 0u; }
}

// ------------------------------------------------- per-batch min/max
// Coords are non-negative, so float ordering == unsigned-bit ordering.
__global__ void k_minmax(const float* __restrict__ coord,
                         const int* __restrict__ offset, int N, int B) {
    __shared__ unsigned smn[MAXB * 3], smx[MAXB * 3];
    __shared__ int soff[MAXB];
    for (int i = threadIdx.x; i < MAXB * 3; i += blockDim.x) {
        smn[i] = 0x7f800000u; smx[i] = 0u;
    }
    if (threadIdx.x < B) soff[threadIdx.x] = offset[threadIdx.x];
    __syncthreads();

    int per = (N + gridDim.x - 1) / gridDim.x;
    int s = blockIdx.x * per;
    int e = min(N, s + per);

    int curB = -1;
    unsigned mn0 = 0, mn1 = 0, mn2 = 0, mx0 = 0, mx1 = 0, mx2 = 0;
    for (int i = s + (int)threadIdx.x; i < e; i += blockDim.x) {
        int lo = 0, hi = B;
        while (lo < hi) { int mid = (lo + hi) >> 1; if (i < soff[mid]) hi = mid; else lo = mid + 1; }
        unsigned x = __float_as_uint(coord[3 * i + 0]);
        unsigned y = __float_as_uint(coord[3 * i + 1]);
        unsigned z = __float_as_uint(coord[3 * i + 2]);
        if (lo != curB) {
            if (curB >= 0) {
                atomicMin(&smn[curB * 3 + 0], mn0); atomicMax(&smx[curB * 3 + 0], mx0);
                atomicMin(&smn[curB * 3 + 1], mn1); atomicMax(&smx[curB * 3 + 1], mx1);
                atomicMin(&smn[curB * 3 + 2], mn2); atomicMax(&smx[curB * 3 + 2], mx2);
            }
            curB = lo;
            mn0 = mx0 = x; mn1 = mx1 = y; mn2 = mx2 = z;
        } else {
            mn0 = min(mn0, x); mx0 = max(mx0, x);
            mn1 = min(mn1, y); mx1 = max(mx1, y);
            mn2 = min(mn2, z); mx2 = max(mx2, z);
        }
    }
    if (curB >= 0) {
        atomicMin(&smn[curB * 3 + 0], mn0); atomicMax(&smx[curB * 3 + 0], mx0);
        atomicMin(&smn[curB * 3 + 1], mn1); atomicMax(&smx[curB * 3 + 1], mx1);
        atomicMin(&smn[curB * 3 + 2], mn2); atomicMax(&smx[curB * 3 + 2], mx2);
    }
    __syncthreads();
    for (int i = threadIdx.x; i < B * 3; i += blockDim.x) {
        if (smn[i] != 0x7f800000u) {
            atomicMin(&g_minbits[i], smn[i]);
            atomicMax(&g_maxbits[i], smx[i]);
        }
    }
}

// ------------------------------------------------- grid extent G
// max over points of floor((c-min)*RINV) == floor((max-min)*RINV) (monotone)
__global__ void k_computeG(int B) {
    __shared__ int sm[128];
    int t = threadIdx.x;
    int v = -1;
    if (t < B * 3 && g_minbits[t] != 0x7f800000u) {
        float mn = __uint_as_float(g_minbits[t]);
        float mx = __uint_as_float(g_maxbits[t]);
        v = (int)floorf(__fmul_rn(__fsub_rn(mx, mn), RINV));
    }
    sm[t] = v;
    __syncthreads();
    for (int o = 64; o > 0; o >>= 1) { if (t < o) sm[t] = max(sm[t], sm[t + o]); __syncthreads(); }
    if (t == 0) {
        int G = sm[0] + 1;
        if (G < 1) G = 1;
        long long G3 = (long long)G * G * G;
        long long nk = (long long)B * G3;
        if (nk > (long long)MAX_KEYS) nk = MAX_KEYS;  // safety clamp
        g_G = G; g_G3 = (int)G3; g_NKEY = (int)nk;
    }
}

// ------------------------------------------------- zeroing
__global__ void k_zero_cells() {
    int n = g_NKEY;
    float4 z = make_float4(0.f, 0.f, 0.f, 0.f);
    int stride = gridDim.x * blockDim.x;
    for (int i = blockIdx.x * blockDim.x + threadIdx.x; i < n; i += stride)
        g_cell[i] = z;
}

__global__ void k_zero_out(float* __restrict__ out, int n) {
    int stride = gridDim.x * blockDim.x;
    int gid = blockIdx.x * blockDim.x + threadIdx.x;
    int n4 = n >> 2;
    float4* o4 = (float4*)out;
    float4 z = make_float4(0.f, 0.f, 0.f, 0.f);
    for (int i = gid; i < n4; i += stride) o4[i] = z;
    for (int i = n4 * 4 + gid; i < n; i += stride) out[i] = 0.f;
}

// ------------------------------------------------- accumulation
__global__ void k_accum(const float* __restrict__ coord,
                        const int* __restrict__ offset, int N, int B) {
    __shared__ int soff[MAXB];
    __shared__ float sstart[MAXB * 3];
    __shared__ int sG;
    if (threadIdx.x < B) soff[threadIdx.x] = offset[threadIdx.x];
    if (threadIdx.x < B * 3) sstart[threadIdx.x] = __uint_as_float(g_minbits[threadIdx.x]);
    if (threadIdx.x == 0) sG = g_G;
    __syncthreads();
    int G = sG;
    int stride = gridDim.x * blockDim.x;
    for (int i = blockIdx.x * blockDim.x + threadIdx.x; i < N; i += stride) {
        int lo = 0, hi = B;
        while (lo < hi) { int mid = (lo + hi) >> 1; if (i < soff[mid]) hi = mid; else lo = mid + 1; }
        int b = lo;
        float x = coord[3 * i + 0];
        float y = coord[3 * i + 1];
        float z = coord[3 * i + 2];
        int gx = (int)floorf(__fmul_rn(__fsub_rn(x, sstart[b * 3 + 0]), RINV));
        int gy = (int)floorf(__fmul_rn(__fsub_rn(y, sstart[b * 3 + 1]), RINV));
        int gz = (int)floorf(__fmul_rn(__fsub_rn(z, sstart[b * 3 + 2]), RINV));
        int key = ((b * G + gx) * G + gy) * G + gz;
        if (key >= 0 && key < MAX_KEYS) {
            asm volatile("red.global.add.v4.f32 [%0], {%1, %2, %3, %4};"
                         :: "l"(&g_cell[key]), "f"(x), "f"(y), "f"(z), "f"(1.0f)
                         : "memory");
        }
    }
}

// ------------------------------------------------- per-block occupancy
__global__ void k_bcount() {
    int nk = g_NKEY;
    int base = blockIdx.x * CHUNK;
    int c = 0;
    for (int j = threadIdx.x; j < CHUNK; j += blockDim.x) {
        int k = base + j;
        if (k < nk && g_cell[k].w > 0.f) c++;
    }
    __shared__ int sred[8];
    for (int o = 16; o > 0; o >>= 1) c += __shfl_down_sync(0xffffffffu, c, o);
    if ((threadIdx.x & 31) == 0) sred[threadIdx.x >> 5] = c;
    __syncthreads();
    if (threadIdx.x == 0) {
        int t = 0;
        for (int w = 0; w < (int)(blockDim.x >> 5); w++) t += sred[w];
        g_bcnt[blockIdx.x] = t;
    }
}

// ------------------------------------------------- scan of block counts
__global__ void k_scan() {   // 1 block, 1024 threads, NSCAN = 3*1024
    __shared__ int sh[1024];
    int t = threadIdx.x;
    int a0 = g_bcnt[3 * t + 0];
    int a1 = g_bcnt[3 * t + 1];
    int a2 = g_bcnt[3 * t + 2];
    int s = a0 + a1 + a2;
    sh[t] = s;
    __syncthreads();
    for (int o = 1; o < 1024; o <<= 1) {
        int v = (t >= o) ? sh[t - o] : 0;
        __syncthreads();
        sh[t] += v;
        __syncthreads();
    }
    int ex = sh[t] - s;
    g_boff[3 * t + 0] = ex;
    g_boff[3 * t + 1] = ex + a0;
    g_boff[3 * t + 2] = ex + a0 + a1;
    if (t == 1023) g_boff[NSCAN] = sh[1023];
}

// ------------------------------------------------- compaction scatter
__global__ void k_scatter(float* __restrict__ out, int N, int B, int full) {
    int nk = g_NKEY;
    const int IT = CHUNK / 256;  // 32 consecutive cells per thread
    int base = blockIdx.x * CHUNK + (int)threadIdx.x * IT;
    int c = 0;
    #pragma unroll 8
    for (int j = 0; j < IT; j++) {
        int k = base + j;
        if (k < nk && g_cell[k].w > 0.f) c++;
    }
    __shared__ int sh[256];
    sh[threadIdx.x] = c;
    __syncthreads();
    for (int o = 1; o < 256; o <<= 1) {
        int v = (threadIdx.x >= (unsigned)o) ? sh[threadIdx.x - o] : 0;
        __syncthreads();
        sh[threadIdx.x] += v;
        __syncthreads();
    }
    int run = g_boff[blockIdx.x] + sh[threadIdx.x] - c;
    float* cntOut = out + (size_t)3 * N + B;
    for (int j = 0; j < IT; j++) {
        int k = base + j;
        if (k < nk) {
            float4 v = g_cell[k];
            if (v.w > 0.f) {
                int o3 = run * 3;
                out[o3 + 0] = __fdiv_rn(v.x, v.w);
                out[o3 + 1] = __fdiv_rn(v.y, v.w);
                out[o3 + 2] = __fdiv_rn(v.z, v.w);
                if (full) cntOut[run] = v.w;
                run++;
            }
        }
    }
}

// ------------------------------------------------- n_o (cumulative voxels/batch)
__global__ void k_no(float* __restrict__ out, int N, int B) {
    int b = blockIdx.x;
    int G3 = g_G3;
    long long pos = (long long)(b + 1) * G3;
    if (pos > g_NKEY) pos = g_NKEY;
    int blkI = (int)(pos / CHUNK);
    int startK = blkI * CHUNK;
    int c = 0;
    for (int k = startK + (int)threadIdx.x; k < (int)pos; k += blockDim.x)
        if (g_cell[k].w > 0.f) c++;
    __shared__ int sred[8];
    for (int o = 16; o > 0; o >>= 1) c += __shfl_down_sync(0xffffffffu, c, o);
    if ((threadIdx.x & 31) == 0) sred[threadIdx.x >> 5] = c;
    __syncthreads();
    if (threadIdx.x == 0) {
        int t = g_boff[blkI];
        for (int w = 0; w < (int)(blockDim.x >> 5); w++) t += sred[w];
        out[(size_t)3 * N + b] = (float)t;
    }
}

// ---------------------------------------------------------------- launch
extern "C" void kernel_launch(void* const* d_in, const int* in_sizes, int n_in,
                              void* d_out, int out_size) {
    const float* coord  = (const float*)d_in[0];
    const int*   offset = (const int*)d_in[1];
    int N = in_sizes[0] / 3;
    int B = in_sizes[1];
    float* out = (float*)d_out;
    int full = ((long long)out_size >= 4LL * N + B) ? 1 : 0;

    k_init<<<1, 128>>>();
    k_minmax<<<1184, 256>>>(coord, offset, N, B);
    k_computeG<<<1, 128>>>(B);
    k_zero_cells<<<2048, 256>>>();
    k_zero_out<<<2048, 256>>>(out, out_size);
    k_accum<<<2368, 256>>>(coord, offset, N, B);
    k_bcount<<<NSCAN, 256>>>();
    k_scan<<<1, 1024>>>();
    k_scatter<<<NSCAN, 256>>>(out, N, B, full);
    if (full) k_no<<<B, 256>>>(out, N, B);
}

// round 7
// speedup vs baseline: 2.2351x; 2.2351x over previous
#include <cuda_runtime.h>

// VSampling: voxel-grid mean pooling, bitmask-compaction design.
//   inputs : coord [N,3] float32, offset [B] int32 (cumulative batch offsets)
//   outputs: n_p [N,3] f32, n_o [B], counts [N]  packed as float32
//
// ARITHMETIC: XLA rewrites x/0.05f -> x * 20.0f (f32(1/f32(0.05)) == 20.0f).
// grid = floor((c - min) * 20.0f) must use explicit rn mul/sub (no FMA).

#define RINV 20.0f
#define MAXB 32
#define MAX_KEYS 25165824                 // capacity: G up to ~116
#define NW_MAX   (MAX_KEYS / 32)          // 786432 bitmask words (3 MB)
#define SCAN_N   (MAX_KEYS / 256)         // 98304 8-word (256-bit) blocks
#define N_MAX    4194304

__device__ uint4  g_bitsv[NW_MAX / 4];    // occupancy bitmask (uint4-aligned)
__device__ int4   g_bcnt8v[SCAN_N / 4];   // per-256-bit-block popcounts
__device__ int4   g_boff8v[SCAN_N / 4 + 1]; // exclusive scan (+ total)
__device__ float4 g_vox[N_MAX];           // compacted {sx,sy,sz,cnt}
__device__ unsigned g_minbits[MAXB * 3];
__device__ unsigned g_maxbits[MAXB * 3];
__device__ int g_G, g_NKEY, g_NW, g_nvox;
__device__ long long g_G3;

// ---------------------------------------------------------------- init
__global__ void k_init() {
    int t = threadIdx.x;
    if (t < MAXB * 3) { g_minbits[t] = 0x7f800000u; g_maxbits[t] = 0u; }
}

// ------------------------------------------------- per-batch min/max
__global__ void k_minmax(const float* __restrict__ coord,
                         const int* __restrict__ offset, int N, int B) {
    __shared__ unsigned smn[MAXB * 3], smx[MAXB * 3];
    __shared__ int soff[MAXB];
    for (int i = threadIdx.x; i < MAXB * 3; i += blockDim.x) {
        smn[i] = 0x7f800000u; smx[i] = 0u;
    }
    if (threadIdx.x < B) soff[threadIdx.x] = offset[threadIdx.x];
    __syncthreads();

    int per = (N + gridDim.x - 1) / gridDim.x;
    int s = blockIdx.x * per;
    int e = min(N, s + per);

    int curB = -1;
    unsigned mn0 = 0, mn1 = 0, mn2 = 0, mx0 = 0, mx1 = 0, mx2 = 0;
    for (int i = s + (int)threadIdx.x; i < e; i += blockDim.x) {
        int lo = 0, hi = B;
        while (lo < hi) { int mid = (lo + hi) >> 1; if (i < soff[mid]) hi = mid; else lo = mid + 1; }
        unsigned x = __float_as_uint(coord[3 * i + 0]);
        unsigned y = __float_as_uint(coord[3 * i + 1]);
        unsigned z = __float_as_uint(coord[3 * i + 2]);
        if (lo != curB) {
            if (curB >= 0) {
                atomicMin(&smn[curB * 3 + 0], mn0); atomicMax(&smx[curB * 3 + 0], mx0);
                atomicMin(&smn[curB * 3 + 1], mn1); atomicMax(&smx[curB * 3 + 1], mx1);
                atomicMin(&smn[curB * 3 + 2], mn2); atomicMax(&smx[curB * 3 + 2], mx2);
            }
            curB = lo;
            mn0 = mx0 = x; mn1 = mx1 = y; mn2 = mx2 = z;
        } else {
            mn0 = min(mn0, x); mx0 = max(mx0, x);
            mn1 = min(mn1, y); mx1 = max(mx1, y);
            mn2 = min(mn2, z); mx2 = max(mx2, z);
        }
    }
    if (curB >= 0) {
        atomicMin(&smn[curB * 3 + 0], mn0); atomicMax(&smx[curB * 3 + 0], mx0);
        atomicMin(&smn[curB * 3 + 1], mn1); atomicMax(&smx[curB * 3 + 1], mx1);
        atomicMin(&smn[curB * 3 + 2], mn2); atomicMax(&smx[curB * 3 + 2], mx2);
    }
    __syncthreads();
    for (int i = threadIdx.x; i < B * 3; i += blockDim.x) {
        if (smn[i] != 0x7f800000u) {
            atomicMin(&g_minbits[i], smn[i]);
            atomicMax(&g_maxbits[i], smx[i]);
        }
    }
}

// ------------------------------------------------- grid extent G
__global__ void k_computeG(int B) {
    __shared__ int sm[128];
    int t = threadIdx.x;
    int v = -1;
    if (t < B * 3 && g_minbits[t] != 0x7f800000u) {
        float mn = __uint_as_float(g_minbits[t]);
        float mx = __uint_as_float(g_maxbits[t]);
        v = (int)floorf(__fmul_rn(__fsub_rn(mx, mn), RINV));
    }
    sm[t] = v;
    __syncthreads();
    for (int o = 64; o > 0; o >>= 1) { if (t < o) sm[t] = max(sm[t], sm[t + o]); __syncthreads(); }
    if (t == 0) {
        int G = sm[0] + 1;
        if (G < 1) G = 1;
        long long G3 = (long long)G * G * G;
        long long nk = (long long)B * G3;
        if (nk > (long long)MAX_KEYS) nk = MAX_KEYS;
        g_G = G; g_G3 = G3;
        g_NKEY = (int)nk;
        g_NW = (int)((nk + 31) >> 5);
    }
}

// ------------------------------------------------- zero bitmask (~3MB)
__global__ void k_zero_bits() {
    int nw4 = (g_NW + 3) >> 2;     // over-zeroing to uint4 boundary is safe
    int stride = gridDim.x * blockDim.x;
    uint4 z = make_uint4(0u, 0u, 0u, 0u);
    for (int i = blockIdx.x * blockDim.x + threadIdx.x; i < nw4; i += stride)
        g_bitsv[i] = z;
}

// ------------------------------------------------- pass1: mark occupancy
__global__ void k_pass1(const float* __restrict__ coord,
                        const int* __restrict__ offset, int N, int B) {
    __shared__ int soff[MAXB];
    __shared__ float sstart[MAXB * 3];
    __shared__ int sG;
    if (threadIdx.x < B) soff[threadIdx.x] = offset[threadIdx.x];
    if (threadIdx.x < B * 3) sstart[threadIdx.x] = __uint_as_float(g_minbits[threadIdx.x]);
    if (threadIdx.x == 0) sG = g_G;
    __syncthreads();
    int G = sG;
    unsigned* bits = (unsigned*)g_bitsv;
    int stride = gridDim.x * blockDim.x;
    for (int i = blockIdx.x * blockDim.x + threadIdx.x; i < N; i += stride) {
        int lo = 0, hi = B;
        while (lo < hi) { int mid = (lo + hi) >> 1; if (i < soff[mid]) hi = mid; else lo = mid + 1; }
        int b = lo;
        float x = coord[3 * i + 0];
        float y = coord[3 * i + 1];
        float z = coord[3 * i + 2];
        int gx = (int)floorf(__fmul_rn(__fsub_rn(x, sstart[b * 3 + 0]), RINV));
        int gy = (int)floorf(__fmul_rn(__fsub_rn(y, sstart[b * 3 + 1]), RINV));
        int gz = (int)floorf(__fmul_rn(__fsub_rn(z, sstart[b * 3 + 2]), RINV));
        int key = ((b * G + gx) * G + gy) * G + gz;
        if (key >= 0 && key < MAX_KEYS)
            atomicOr(&bits[key >> 5], 1u << (key & 31));
    }
}

// ------------------------------------------------- per-256bit-block counts
__global__ void k_bcount8() {
    int gid = blockIdx.x * blockDim.x + threadIdx.x;   // one thread = 4 blocks
    if (gid >= SCAN_N / 4) return;
    int NW = g_NW;
    const unsigned* bits = (const unsigned*)g_bitsv;
    int wbase = gid * 32;
    int c[4] = {0, 0, 0, 0};
    if (wbase + 31 < NW) {
        #pragma unroll
        for (int j = 0; j < 4; j++)
            #pragma unroll
            for (int w = 0; w < 8; w++)
                c[j] += __popc(bits[wbase + j * 8 + w]);
    } else {
        for (int j = 0; j < 4; j++)
            for (int w = 0; w < 8; w++) {
                int idx = wbase + j * 8 + w;
                if (idx < NW) c[j] += __popc(bits[idx]);
            }
    }
    g_bcnt8v[gid] = make_int4(c[0], c[1], c[2], c[3]);
}

// ------------------------------------------------- scan (1 block, 1024 thr)
__global__ void k_scan() {
    __shared__ int sh[1024];
    const int PT = SCAN_N / 4 / 1024;   // 24 int4 per thread
    int t = threadIdx.x;
    int base = t * PT;
    int tot = 0;
    #pragma unroll 4
    for (int i = 0; i < PT; i++) {
        int4 v = g_bcnt8v[base + i];
        tot += v.x + v.y + v.z + v.w;
    }
    sh[t] = tot;
    __syncthreads();
    for (int o = 1; o < 1024; o <<= 1) {
        int v = (t >= o) ? sh[t - o] : 0;
        __syncthreads();
        sh[t] += v;
        __syncthreads();
    }
    int run = sh[t] - tot;
    #pragma unroll 4
    for (int i = 0; i < PT; i++) {
        int4 v = g_bcnt8v[base + i];
        int4 o;
        o.x = run; run += v.x;
        o.y = run; run += v.y;
        o.z = run; run += v.z;
        o.w = run; run += v.w;
        g_boff8v[base + i] = o;
    }
    if (t == 1023) {
        ((int*)g_boff8v)[SCAN_N] = run;
        g_nvox = run;
    }
}

// ------------------------------------------------- zero compact scratch
__global__ void k_zero_vox() {
    int n = g_nvox;
    float4 z = make_float4(0.f, 0.f, 0.f, 0.f);
    int stride = gridDim.x * blockDim.x;
    for (int i = blockIdx.x * blockDim.x + threadIdx.x; i < n; i += stride)
        g_vox[i] = z;
}

// ------------------------------------------------- pass2: rank + accumulate
__global__ void k_pass2(const float* __restrict__ coord,
                        const int* __restrict__ offset, int N, int B) {
    __shared__ int soff[MAXB];
    __shared__ float sstart[MAXB * 3];
    __shared__ int sG;
    if (threadIdx.x < B) soff[threadIdx.x] = offset[threadIdx.x];
    if (threadIdx.x < B * 3) sstart[threadIdx.x] = __uint_as_float(g_minbits[threadIdx.x]);
    if (threadIdx.x == 0) sG = g_G;
    __syncthreads();
    int G = sG;
    const int* boff = (const int*)g_boff8v;
    int stride = gridDim.x * blockDim.x;
    for (int i = blockIdx.x * blockDim.x + threadIdx.x; i < N; i += stride) {
        int lo = 0, hi = B;
        while (lo < hi) { int mid = (lo + hi) >> 1; if (i < soff[mid]) hi = mid; else lo = mid + 1; }
        int b = lo;
        float x = coord[3 * i + 0];
        float y = coord[3 * i + 1];
        float z = coord[3 * i + 2];
        int gx = (int)floorf(__fmul_rn(__fsub_rn(x, sstart[b * 3 + 0]), RINV));
        int gy = (int)floorf(__fmul_rn(__fsub_rn(y, sstart[b * 3 + 1]), RINV));
        int gz = (int)floorf(__fmul_rn(__fsub_rn(z, sstart[b * 3 + 2]), RINV));
        int key = ((b * G + gx) * G + gy) * G + gz;
        if (key < 0 || key >= MAX_KEYS) continue;
        int blk = key >> 8;
        int wi  = (key >> 5) & 7;
        unsigned pmask = (1u << (key & 31)) - 1u;
        uint4 A = g_bitsv[blk * 2 + 0];
        uint4 Bq = g_bitsv[blk * 2 + 1];
        unsigned wv0 = A.x, wv1 = A.y, wv2 = A.z, wv3 = A.w;
        unsigned wv4 = Bq.x, wv5 = Bq.y, wv6 = Bq.z, wv7 = Bq.w;
        int r = boff[blk];
        // bits strictly below key: full words w<wi, partial word w==wi
        #pragma unroll
        {
            unsigned m;
            m = (0 < wi) ? 0xffffffffu : ((0 == wi) ? pmask : 0u); r += __popc(wv0 & m);
            m = (1 < wi) ? 0xffffffffu : ((1 == wi) ? pmask : 0u); r += __popc(wv1 & m);
            m = (2 < wi) ? 0xffffffffu : ((2 == wi) ? pmask : 0u); r += __popc(wv2 & m);
            m = (3 < wi) ? 0xffffffffu : ((3 == wi) ? pmask : 0u); r += __popc(wv3 & m);
            m = (4 < wi) ? 0xffffffffu : ((4 == wi) ? pmask : 0u); r += __popc(wv4 & m);
            m = (5 < wi) ? 0xffffffffu : ((5 == wi) ? pmask : 0u); r += __popc(wv5 & m);
            m = (6 < wi) ? 0xffffffffu : ((6 == wi) ? pmask : 0u); r += __popc(wv6 & m);
            m = (7 == wi) ? pmask : 0u;                            r += __popc(wv7 & m);
        }
        if (r >= 0 && r < N_MAX) {
            asm volatile("red.global.add.v4.f32 [%0], {%1, %2, %3, %4};"
                         :: "l"(&g_vox[r]), "f"(x), "f"(y), "f"(z), "f"(1.0f)
                         : "memory");
        }
    }
}

// ------------------------------------------------- finalize means
__global__ void k_finalize(float* __restrict__ out, int N, int B, int full) {
    int n = g_nvox;
    float* cntOut = out + (size_t)3 * N + B;
    int stride = gridDim.x * blockDim.x;
    for (int j = blockIdx.x * blockDim.x + threadIdx.x; j < n; j += stride) {
        float4 v = g_vox[j];
        float w = (v.w > 0.f) ? v.w : 1.f;
        out[3 * j + 0] = __fdiv_rn(v.x, w);
        out[3 * j + 1] = __fdiv_rn(v.y, w);
        out[3 * j + 2] = __fdiv_rn(v.z, w);
        if (full) cntOut[j] = v.w;
    }
}

// ------------------------------------------------- zero output tail
__global__ void k_ztail(float* __restrict__ out, int N, int B, int full) {
    int nv = g_nvox;
    int stride = gridDim.x * blockDim.x;
    int gid = blockIdx.x * blockDim.x + threadIdx.x;
    int lenA = 3 * N - 3 * nv;
    for (int i = gid; i < lenA; i += stride) out[3 * nv + i] = 0.f;
    if (full) {
        float* cntOut = out + (size_t)3 * N + B;
        int lenB = N - nv;
        for (int i = gid; i < lenB; i += stride) cntOut[nv + i] = 0.f;
    }
}

// ------------------------------------------------- n_o (cumulative voxels/batch)
__global__ void k_no(float* __restrict__ out, int N, int B) {
    int t = threadIdx.x;
    if (t >= B) return;
    long long pos = (long long)(t + 1) * g_G3;
    if (pos > (long long)g_NKEY) pos = g_NKEY;
    int blk = (int)(pos >> 8);
    int c = ((const int*)g_boff8v)[blk];
    const unsigned* bits = (const unsigned*)g_bitsv;
    int fullw = (int)((pos >> 5) & 7);
    int rem   = (int)(pos & 31);
    for (int w = 0; w < fullw; w++) c += __popc(bits[blk * 8 + w]);
    if (rem) c += __popc(bits[blk * 8 + fullw] & ((1u << rem) - 1u));
    out[(size_t)3 * N + t] = (float)c;
}

// ---------------------------------------------------------------- launch
extern "C" void kernel_launch(void* const* d_in, const int* in_sizes, int n_in,
                              void* d_out, int out_size) {
    const float* coord  = (const float*)d_in[0];
    const int*   offset = (const int*)d_in[1];
    int N = in_sizes[0] / 3;
    int B = in_sizes[1];
    float* out = (float*)d_out;
    int full = ((long long)out_size >= 4LL * N + B) ? 1 : 0;

    k_init<<<1, 128>>>();
    k_minmax<<<1184, 256>>>(coord, offset, N, B);
    k_computeG<<<1, 128>>>(B);
    k_zero_bits<<<768, 256>>>();
    k_pass1<<<2368, 256>>>(coord, offset, N, B);
    k_bcount8<<<96, 256>>>();
    k_scan<<<1, 1024>>>();
    k_zero_vox<<<2048, 256>>>();
    k_pass2<<<2368, 256>>>(coord, offset, N, B);
    k_finalize<<<2048, 256>>>(out, N, B, full);
    k_ztail<<<512, 256>>>(out, N, B, full);
    if (full) k_no<<<1, 32>>>(out, N, B);
}